// round 3
// baseline (speedup 1.0000x reference)
#include <cuda_runtime.h>
#include <math_constants.h>

// Problem constants
#define NROWS 16384   // 64 * 256
#define DIM   1024
#define CB    4096

// Output layout (flattened tuple, float32):
//   quantized_st [16384*1024], codes [16384], probs [16384*4096], vq_loss [1]
#define QUANT_OFF 0
#define CODES_OFF 16777216
#define PROBS_OFF 16793600
#define LOSS_OFF  83902464

// Scratch (device globals — no allocations allowed)
__device__ float  g_S[(size_t)NROWS * CB];   // s[n][c] = ||c||^2 - 2 x.c  (256 MiB)
__device__ float  g_cnorm[CB];
__device__ double g_loss;

// ---------------------------------------------------------------------------
// Kernel 0: codebook norms + zero the loss accumulator
// ---------------------------------------------------------------------------
__global__ __launch_bounds__(256) void cnorm_kernel(const float* __restrict__ cb) {
    int row = blockIdx.x;                       // 4096 rows
    const float4* c4 = (const float4*)(cb + (size_t)row * DIM);
    float4 v = c4[threadIdx.x];                 // 256 threads * 4 = 1024
    float s = v.x * v.x + v.y * v.y + v.z * v.z + v.w * v.w;
    #pragma unroll
    for (int o = 16; o > 0; o >>= 1) s += __shfl_xor_sync(0xffffffffu, s, o);
    __shared__ float ws[8];
    if ((threadIdx.x & 31) == 0) ws[threadIdx.x >> 5] = s;
    __syncthreads();
    if (threadIdx.x == 0) {
        float t = 0.f;
        #pragma unroll
        for (int i = 0; i < 8; i++) t += ws[i];
        g_cnorm[row] = t;
        if (row == 0) g_loss = 0.0;
    }
}

// ---------------------------------------------------------------------------
// Kernel 1: SGEMM  s[m][n] = cnorm[n] - 2 * (A[m,:] . B[n,:])
// A = slot [16384,1024], B = codebook [4096,1024], both K-contiguous.
// 128x128 tile, BK=16, 256 threads, 8x8 per thread.
// ---------------------------------------------------------------------------
#define BM 128
#define BN 128
#define BK 16

__global__ __launch_bounds__(256) void gemm_kernel(const float* __restrict__ A,
                                                   const float* __restrict__ B) {
    __shared__ float As[BK][BM];
    __shared__ float Bs[BK][BN];

    const int tid   = threadIdx.x;
    const int m0    = blockIdx.y * BM;
    const int n0    = blockIdx.x * BN;
    const int lrow  = tid >> 2;     // 0..63
    const int lcol4 = tid & 3;      // float4 index within 16 k-values

    const int tx = tid & 15;        // n-group
    const int ty = tid >> 4;        // m-group

    float acc[8][8] = {};

    for (int k0 = 0; k0 < DIM; k0 += BK) {
        // Load A tile (128 x 16) transposed into As[k][m]
        #pragma unroll
        for (int r = 0; r < 2; r++) {
            int row = lrow + r * 64;
            float4 v = *(const float4*)(A + (size_t)(m0 + row) * DIM + k0 + lcol4 * 4);
            As[lcol4 * 4 + 0][row] = v.x;
            As[lcol4 * 4 + 1][row] = v.y;
            As[lcol4 * 4 + 2][row] = v.z;
            As[lcol4 * 4 + 3][row] = v.w;
        }
        // Load B tile (128 x 16) transposed into Bs[k][n]
        #pragma unroll
        for (int r = 0; r < 2; r++) {
            int row = lrow + r * 64;
            float4 v = *(const float4*)(B + (size_t)(n0 + row) * DIM + k0 + lcol4 * 4);
            Bs[lcol4 * 4 + 0][row] = v.x;
            Bs[lcol4 * 4 + 1][row] = v.y;
            Bs[lcol4 * 4 + 2][row] = v.z;
            Bs[lcol4 * 4 + 3][row] = v.w;
        }
        __syncthreads();

        #pragma unroll
        for (int k = 0; k < BK; k++) {
            float ra[8], rb[8];
            const float4* a4 = (const float4*)(&As[k][ty * 8]);
            const float4* b4 = (const float4*)(&Bs[k][tx * 8]);
            float4 a0 = a4[0], a1 = a4[1];
            float4 b0 = b4[0], b1 = b4[1];
            ra[0]=a0.x; ra[1]=a0.y; ra[2]=a0.z; ra[3]=a0.w;
            ra[4]=a1.x; ra[5]=a1.y; ra[6]=a1.z; ra[7]=a1.w;
            rb[0]=b0.x; rb[1]=b0.y; rb[2]=b0.z; rb[3]=b0.w;
            rb[4]=b1.x; rb[5]=b1.y; rb[6]=b1.z; rb[7]=b1.w;
            #pragma unroll
            for (int i = 0; i < 8; i++)
                #pragma unroll
                for (int j = 0; j < 8; j++)
                    acc[i][j] += ra[i] * rb[j];
        }
        __syncthreads();
    }

    // Epilogue: s = cnorm[n] - 2*dot
    #pragma unroll
    for (int i = 0; i < 8; i++) {
        int m = m0 + ty * 8 + i;
        float* srow = g_S + (size_t)m * CB;
        #pragma unroll
        for (int j = 0; j < 8; j += 4) {
            int n = n0 + tx * 8 + j;
            float4 o;
            o.x = g_cnorm[n + 0] - 2.f * acc[i][j + 0];
            o.y = g_cnorm[n + 1] - 2.f * acc[i][j + 1];
            o.z = g_cnorm[n + 2] - 2.f * acc[i][j + 2];
            o.w = g_cnorm[n + 3] - 2.f * acc[i][j + 3];
            *(float4*)(srow + n) = o;
        }
    }
}

// ---------------------------------------------------------------------------
// Kernel 2: per-row argmin(+double refinement), softmax -> probs,
//           gather -> quantized, loss accumulation, codes.
// One CTA (256 threads) per row; each thread owns 16 columns.
// ---------------------------------------------------------------------------
__global__ __launch_bounds__(256) void row_kernel(const float* __restrict__ slot,
                                                  const float* __restrict__ cb,
                                                  float* __restrict__ out) {
    const int row = blockIdx.x;
    const int tid = threadIdx.x;
    const float* srow = g_S + (size_t)row * CB;

    // --- load row, track local top-2 (first-occurrence tie-break) ---
    float v[16];
    float m1 = CUDART_INF_F, m2 = CUDART_INF_F;
    int   i1 = CB, i2 = CB;
    #pragma unroll
    for (int i = 0; i < 16; i++) {
        int idx = tid + i * 256;
        float x = srow[idx];
        v[i] = x;
        if (x < m1 || (x == m1 && idx < i1)) {
            m2 = m1; i2 = i1; m1 = x; i1 = idx;
        } else if (x < m2 || (x == m2 && idx < i2)) {
            m2 = x; i2 = idx;
        }
    }

    // --- block-wide top-2 reduction ---
    __shared__ float rm1[256], rm2[256];
    __shared__ int   ri1[256], ri2[256];
    rm1[tid] = m1; rm2[tid] = m2; ri1[tid] = i1; ri2[tid] = i2;
    __syncthreads();
    for (int s = 128; s > 0; s >>= 1) {
        if (tid < s) {
            float a1 = rm1[tid], b1 = rm1[tid + s];
            int   ai = ri1[tid], bi = ri1[tid + s];
            float a2 = rm2[tid], b2 = rm2[tid + s];
            int  a2i = ri2[tid], b2i = ri2[tid + s];
            bool af = (a1 < b1) || (a1 == b1 && ai < bi);
            if (af) {
                bool t = (a2 < b1) || (a2 == b1 && a2i < bi);
                rm2[tid] = t ? a2 : b1;  ri2[tid] = t ? a2i : bi;
            } else {
                rm1[tid] = b1; ri1[tid] = bi;
                bool t = (b2 < a1) || (b2 == a1 && b2i < ai);
                rm2[tid] = t ? b2 : a1;  ri2[tid] = t ? b2i : ai;
            }
        }
        __syncthreads();
    }
    const float gm1 = rm1[0]; const int gi1 = ri1[0];
    const float gm2 = rm2[0]; const int gi2 = ri2[0];
    __syncthreads();   // done reading rm*/ri* before any reuse

    // --- rare-path double-precision refinement of argmin ---
    __shared__ int    s_code;
    __shared__ double sd[256];
    if (gm2 - gm1 < 1e-3f) {
        const float* x  = slot + (size_t)row * DIM;
        const float* c1 = cb + (size_t)gi1 * DIM;
        const float* c2 = cb + (size_t)gi2 * DIM;
        double d1 = 0.0, d2 = 0.0;
        for (int k = tid; k < DIM; k += 256) {
            double xv = (double)x[k];
            double a  = (double)c1[k];
            double b  = (double)c2[k];
            d1 += a * (a - 2.0 * xv);
            d2 += b * (b - 2.0 * xv);
        }
        sd[tid] = d1; __syncthreads();
        for (int s = 128; s > 0; s >>= 1) { if (tid < s) sd[tid] += sd[tid + s]; __syncthreads(); }
        double D1 = sd[0]; __syncthreads();
        sd[tid] = d2; __syncthreads();
        for (int s = 128; s > 0; s >>= 1) { if (tid < s) sd[tid] += sd[tid + s]; __syncthreads(); }
        double D2 = sd[0];
        if (tid == 0)
            s_code = (D2 < D1 || (D2 == D1 && gi2 < gi1)) ? gi2 : gi1;
    } else if (tid == 0) {
        s_code = gi1;
    }
    __syncthreads();
    const int code = s_code;

    // --- softmax over -s (row constant ||x||^2 cancels) ---
    float lsum = 0.f;
    #pragma unroll
    for (int i = 0; i < 16; i++) {
        float e = __expf(gm1 - v[i]);   // arg <= 0
        v[i] = e;
        lsum += e;
    }
    rm1[tid] = lsum; __syncthreads();
    for (int s = 128; s > 0; s >>= 1) { if (tid < s) rm1[tid] += rm1[tid + s]; __syncthreads(); }
    const float inv = 1.0f / rm1[0];
    float* probs = out + PROBS_OFF + (size_t)row * CB;
    #pragma unroll
    for (int i = 0; i < 16; i++)
        probs[tid + i * 256] = v[i] * inv;

    // --- quantized gather + loss contribution ---
    const float4* c4 = (const float4*)(cb + (size_t)code * DIM);
    const float4* x4 = (const float4*)(slot + (size_t)row * DIM);
    float4 q = c4[tid];
    float4 x = x4[tid];
    ((float4*)(out + QUANT_OFF + (size_t)row * DIM))[tid] = q;
    float dx = x.x - q.x, dy = x.y - q.y, dz = x.z - q.z, dw = x.w - q.w;
    float ls = dx * dx + dy * dy + dz * dz + dw * dw;

    __syncthreads();                 // rm1 reuse
    rm1[tid] = ls; __syncthreads();
    for (int s = 128; s > 0; s >>= 1) { if (tid < s) rm1[tid] += rm1[tid + s]; __syncthreads(); }
    if (tid == 0) {
        atomicAdd(&g_loss, (double)rm1[0]);
        out[CODES_OFF + row] = (float)code;
    }
}

// ---------------------------------------------------------------------------
// Kernel 3: finalize vq_loss = 1.25 * mean((x - q)^2)
// ---------------------------------------------------------------------------
__global__ void finish_kernel(float* __restrict__ out) {
    out[LOSS_OFF] = (float)(1.25 * g_loss / (double)((size_t)NROWS * DIM));
}

// ---------------------------------------------------------------------------
extern "C" void kernel_launch(void* const* d_in, const int* in_sizes, int n_in,
                              void* d_out, int out_size) {
    const float* slot = (const float*)d_in[0];   // [64,256,1024] f32
    const float* cb   = (const float*)d_in[1];   // [4096,1024]  f32
    float* out = (float*)d_out;

    cnorm_kernel<<<CB, 256>>>(cb);
    dim3 grid(CB / BN, NROWS / BM);              // 32 x 128
    gemm_kernel<<<grid, 256>>>(slot, cb);
    row_kernel<<<NROWS, 256>>>(slot, cb, out);
    finish_kernel<<<1, 1>>>(out);
}

// round 9
// speedup vs baseline: 2.5038x; 2.5038x over previous
#include <cuda_runtime.h>
#include <cuda_bf16.h>
#include <math_constants.h>
#include <cstdint>

// Problem constants
#define NROWS 16384   // 64 * 256
#define DIM   1024
#define CB    4096

// Output layout (flattened tuple, float32):
//   quantized_st [16384*1024], codes [16384], probs [16384*4096], vq_loss [1]
#define QUANT_OFF 0
#define CODES_OFF 16777216
#define PROBS_OFF 16793600
#define LOSS_OFF  83902464

// ---------------------------------------------------------------------------
// Scratch (device globals — no allocations allowed)
// ---------------------------------------------------------------------------
__device__ float  g_S[(size_t)NROWS * CB];            // 256 MiB distances
__device__ float  g_cnorm[CB];
__device__ double g_loss;
__device__ __nv_bfloat16 g_Ahi[(size_t)NROWS * DIM];  // 32 MiB
__device__ __nv_bfloat16 g_Alo[(size_t)NROWS * DIM];  // 32 MiB
__device__ __nv_bfloat16 g_Bhi[(size_t)CB * DIM];     //  8 MiB
__device__ __nv_bfloat16 g_Blo[(size_t)CB * DIM];     //  8 MiB

// ---------------------------------------------------------------------------
// Low-level helpers (all plain sm_80+ PTX — no tcgen05 / no 'a' features)
// ---------------------------------------------------------------------------
__device__ __forceinline__ uint32_t smem_u32(const void* p) {
    uint32_t a;
    asm("{ .reg .u64 t; cvta.to.shared.u64 t, %1; cvt.u32.u64 %0, t; }"
        : "=r"(a) : "l"(p));
    return a;
}

__device__ __forceinline__ void cp_async16(uint32_t saddr, const void* gaddr) {
    asm volatile("cp.async.cg.shared.global [%0], [%1], 16;"
                 :: "r"(saddr), "l"(gaddr));
}
#define CP_COMMIT() asm volatile("cp.async.commit_group;" ::: "memory")
#define CP_WAIT_1() asm volatile("cp.async.wait_group 1;" ::: "memory")
#define CP_WAIT_0() asm volatile("cp.async.wait_group 0;" ::: "memory")

__device__ __forceinline__ uint32_t lds32(uint32_t a) {
    uint32_t v;
    asm("ld.shared.b32 %0, [%1];" : "=r"(v) : "r"(a));
    return v;
}

__device__ __forceinline__ void mma16816(float* c, const uint32_t* a, const uint32_t* b) {
    asm volatile(
        "mma.sync.aligned.m16n8k16.row.col.f32.bf16.bf16.f32 "
        "{%0,%1,%2,%3}, {%4,%5,%6,%7}, {%8,%9}, {%0,%1,%2,%3};"
        : "+f"(c[0]), "+f"(c[1]), "+f"(c[2]), "+f"(c[3])
        : "r"(a[0]), "r"(a[1]), "r"(a[2]), "r"(a[3]), "r"(b[0]), "r"(b[1]));
}

// ---------------------------------------------------------------------------
// Kernel 0: codebook norms + zero the loss accumulator
// ---------------------------------------------------------------------------
__global__ __launch_bounds__(256) void cnorm_kernel(const float* __restrict__ cb) {
    int row = blockIdx.x;
    const float4* c4 = (const float4*)(cb + (size_t)row * DIM);
    float4 v = c4[threadIdx.x];
    float s = v.x * v.x + v.y * v.y + v.z * v.z + v.w * v.w;
    #pragma unroll
    for (int o = 16; o > 0; o >>= 1) s += __shfl_xor_sync(0xffffffffu, s, o);
    __shared__ float ws[8];
    if ((threadIdx.x & 31) == 0) ws[threadIdx.x >> 5] = s;
    __syncthreads();
    if (threadIdx.x == 0) {
        float t = 0.f;
        #pragma unroll
        for (int i = 0; i < 8; i++) t += ws[i];
        g_cnorm[row] = t;
        if (row == 0) g_loss = 0.0;
    }
}

// ---------------------------------------------------------------------------
// Kernel 0b: split fp32 inputs into bf16 hi/lo pairs
// ---------------------------------------------------------------------------
#define A_F4 ((size_t)NROWS * DIM / 4)   // 4194304
#define B_F4 ((size_t)CB * DIM / 4)      // 1048576

__global__ __launch_bounds__(256) void split_kernel(const float* __restrict__ A,
                                                    const float* __restrict__ B) {
    size_t i4 = (size_t)blockIdx.x * 256 + threadIdx.x;
    float4 v;
    __nv_bfloat16 *hi, *lo;
    size_t e;
    if (i4 < A_F4) {
        v = ((const float4*)A)[i4];
        hi = g_Ahi; lo = g_Alo; e = i4 * 4;
    } else {
        size_t j = i4 - A_F4;
        v = ((const float4*)B)[j];
        hi = g_Bhi; lo = g_Blo; e = j * 4;
    }
    __nv_bfloat16 h0 = __float2bfloat16_rn(v.x);
    __nv_bfloat16 h1 = __float2bfloat16_rn(v.y);
    __nv_bfloat16 h2 = __float2bfloat16_rn(v.z);
    __nv_bfloat16 h3 = __float2bfloat16_rn(v.w);
    __nv_bfloat16 l0 = __float2bfloat16_rn(v.x - __bfloat162float(h0));
    __nv_bfloat16 l1 = __float2bfloat16_rn(v.y - __bfloat162float(h1));
    __nv_bfloat16 l2 = __float2bfloat16_rn(v.z - __bfloat162float(h2));
    __nv_bfloat16 l3 = __float2bfloat16_rn(v.w - __bfloat162float(h3));
    __nv_bfloat162* hp = (__nv_bfloat162*)(hi + e);
    __nv_bfloat162* lp = (__nv_bfloat162*)(lo + e);
    hp[0] = __halves2bfloat162(h0, h1);
    hp[1] = __halves2bfloat162(h2, h3);
    lp[0] = __halves2bfloat162(l0, l1);
    lp[1] = __halves2bfloat162(l2, l3);
}

// ---------------------------------------------------------------------------
// Kernel 1: bf16x3 HMMA GEMM -> g_S[m][n] = cnorm[n] - 2 * dot(A_m, B_n)
// 128x128 CTA tile, BK=32, cp.async double buffer, 256 threads (8 warps).
// Warp layout: 2(M) x 4(N) -> each warp owns 64x32.
// SMEM tiles padded to 80B rows (40 bf16) => conflict-free fragment LDS.
// ---------------------------------------------------------------------------
#define GBM 128
#define GBN 128
#define BKC 32                  // K per chunk (bf16 elems)
#define NCHUNK (DIM / BKC)      // 32
#define PKROW 40                // padded row length (bf16) = 80 bytes
#define ROWB  (PKROW * 2)       // 80
#define TILE_B (128 * ROWB)     // 10240 bytes per tile
#define STAGE_BYTES (4 * TILE_B)            // 40960
#define GEMM_SMEM_TOTAL (2 * STAGE_BYTES)   // 81920

__device__ __forceinline__ void load_stage(uint32_t st, int m0, int n0, int k0, int tid) {
    // 4 tiles x 128 rows x 64B (4 x 16B chunks). 2048 cp.async / 256 thr = 8 each.
    const char* gbase[4] = {(const char*)g_Ahi, (const char*)g_Alo,
                            (const char*)g_Bhi, (const char*)g_Blo};
    #pragma unroll
    for (int tile = 0; tile < 4; tile++) {
        int rc0 = (tile < 2) ? m0 : n0;
        #pragma unroll
        for (int r = 0; r < 2; r++) {
            int idx = tid + r * 256;          // 0..511
            int row = idx >> 2;               // 0..127
            int ch  = idx & 3;                // 0..3
            uint32_t saddr = st + tile * TILE_B + (uint32_t)row * ROWB + (uint32_t)ch * 16;
            const char* g = gbase[tile] + ((size_t)(rc0 + row) * DIM + k0) * 2 + (size_t)ch * 16;
            cp_async16(saddr, g);
        }
    }
}

__global__ __launch_bounds__(256, 2) void gemm_kernel() {
    extern __shared__ __align__(128) char smem[];
    const uint32_t smem_base = smem_u32(smem);
    const int tid   = threadIdx.x;
    const int wid   = tid >> 5;
    const int lane  = tid & 31;
    const int group = lane >> 2;    // 0..7
    const int tig   = lane & 3;     // 0..3
    const int warp_m = wid >> 2;    // 0..1 (64 rows each)
    const int warp_n = wid & 3;     // 0..3 (32 cols each)
    const int n0 = blockIdx.x * GBN;
    const int m0 = blockIdx.y * GBM;

    float acc[4][4][4];             // [mt][nt][frag]
    #pragma unroll
    for (int i = 0; i < 4; i++)
        #pragma unroll
        for (int j = 0; j < 4; j++)
            #pragma unroll
            for (int k = 0; k < 4; k++) acc[i][j][k] = 0.f;

    // Prologue: chunks 0 and 1
    load_stage(smem_base, m0, n0, 0, tid);
    CP_COMMIT();
    load_stage(smem_base + STAGE_BYTES, m0, n0, BKC, tid);
    CP_COMMIT();

    #pragma unroll 1
    for (int i = 0; i < NCHUNK; i++) {
        if (i < NCHUNK - 1) CP_WAIT_1(); else CP_WAIT_0();
        __syncthreads();
        const uint32_t st = smem_base + (i & 1) * STAGE_BYTES;

        #pragma unroll
        for (int k16 = 0; k16 < 2; k16++) {
            const uint32_t kb = k16 * 32;   // 16 bf16 = 32 bytes

            uint32_t a[4][4], bh[4][2], bl[4][2];
            // A_hi fragments (tile 0)
            #pragma unroll
            for (int mt = 0; mt < 4; mt++) {
                uint32_t ad = st + (uint32_t)(warp_m * 64 + mt * 16 + group) * ROWB + kb + tig * 4;
                a[mt][0] = lds32(ad);
                a[mt][1] = lds32(ad + 8 * ROWB);
                a[mt][2] = lds32(ad + 16);
                a[mt][3] = lds32(ad + 8 * ROWB + 16);
            }
            // B_hi (tile 2) and B_lo (tile 3) fragments
            #pragma unroll
            for (int nt = 0; nt < 4; nt++) {
                uint32_t bd = st + 2 * TILE_B + (uint32_t)(warp_n * 32 + nt * 8 + group) * ROWB + kb + tig * 4;
                bh[nt][0] = lds32(bd);
                bh[nt][1] = lds32(bd + 16);
                bl[nt][0] = lds32(bd + TILE_B);
                bl[nt][1] = lds32(bd + TILE_B + 16);
            }
            // hi*hi and hi*lo
            #pragma unroll
            for (int mt = 0; mt < 4; mt++)
                #pragma unroll
                for (int nt = 0; nt < 4; nt++) {
                    mma16816(acc[mt][nt], a[mt], bh[nt]);
                    mma16816(acc[mt][nt], a[mt], bl[nt]);
                }
            // A_lo fragments (tile 1), reuse B_hi: lo*hi
            #pragma unroll
            for (int mt = 0; mt < 4; mt++) {
                uint32_t ad = st + TILE_B + (uint32_t)(warp_m * 64 + mt * 16 + group) * ROWB + kb + tig * 4;
                a[mt][0] = lds32(ad);
                a[mt][1] = lds32(ad + 8 * ROWB);
                a[mt][2] = lds32(ad + 16);
                a[mt][3] = lds32(ad + 8 * ROWB + 16);
            }
            #pragma unroll
            for (int mt = 0; mt < 4; mt++)
                #pragma unroll
                for (int nt = 0; nt < 4; nt++)
                    mma16816(acc[mt][nt], a[mt], bh[nt]);
        }

        __syncthreads();
        if (i + 2 < NCHUNK) {
            load_stage(st, m0, n0, (i + 2) * BKC, tid);
            CP_COMMIT();
        }
    }

    // Epilogue: s = cnorm[n] - 2*dot
    #pragma unroll
    for (int nt = 0; nt < 4; nt++) {
        const int n = n0 + warp_n * 32 + nt * 8 + tig * 2;
        const float2 cn = *(const float2*)(g_cnorm + n);
        #pragma unroll
        for (int mt = 0; mt < 4; mt++) {
            const int m = m0 + warp_m * 64 + mt * 16 + group;
            float2 o0, o1;
            o0.x = cn.x - 2.f * acc[mt][nt][0];
            o0.y = cn.y - 2.f * acc[mt][nt][1];
            o1.x = cn.x - 2.f * acc[mt][nt][2];
            o1.y = cn.y - 2.f * acc[mt][nt][3];
            *(float2*)(g_S + (size_t)m * CB + n) = o0;
            *(float2*)(g_S + (size_t)(m + 8) * CB + n) = o1;
        }
    }
}

// ---------------------------------------------------------------------------
// Kernel 2: per-row argmin(+double refinement), softmax -> probs,
//           gather -> quantized, loss accumulation, codes.
// ---------------------------------------------------------------------------
__global__ __launch_bounds__(256) void row_kernel(const float* __restrict__ slot,
                                                  const float* __restrict__ cb,
                                                  float* __restrict__ out) {
    const int row = blockIdx.x;
    const int tid = threadIdx.x;
    const float* srow = g_S + (size_t)row * CB;

    // --- load row, track local top-2 (first-occurrence tie-break) ---
    float v[16];
    float m1 = CUDART_INF_F, m2 = CUDART_INF_F;
    int   i1 = CB, i2 = CB;
    #pragma unroll
    for (int i = 0; i < 16; i++) {
        int idx = tid + i * 256;
        float x = srow[idx];
        v[i] = x;
        if (x < m1 || (x == m1 && idx < i1)) {
            m2 = m1; i2 = i1; m1 = x; i1 = idx;
        } else if (x < m2 || (x == m2 && idx < i2)) {
            m2 = x; i2 = idx;
        }
    }

    // --- block-wide top-2 reduction ---
    __shared__ float rm1[256], rm2[256];
    __shared__ int   ri1[256], ri2[256];
    rm1[tid] = m1; rm2[tid] = m2; ri1[tid] = i1; ri2[tid] = i2;
    __syncthreads();
    for (int s = 128; s > 0; s >>= 1) {
        if (tid < s) {
            float a1 = rm1[tid], b1 = rm1[tid + s];
            int   ai = ri1[tid], bi = ri1[tid + s];
            float a2 = rm2[tid], b2 = rm2[tid + s];
            int  a2i = ri2[tid], b2i = ri2[tid + s];
            bool af = (a1 < b1) || (a1 == b1 && ai < bi);
            if (af) {
                bool t = (a2 < b1) || (a2 == b1 && a2i < bi);
                rm2[tid] = t ? a2 : b1;  ri2[tid] = t ? a2i : bi;
            } else {
                rm1[tid] = b1; ri1[tid] = bi;
                bool t = (b2 < a1) || (b2 == a1 && b2i < ai);
                rm2[tid] = t ? b2 : a1;  ri2[tid] = t ? b2i : ai;
            }
        }
        __syncthreads();
    }
    const float gm1 = rm1[0]; const int gi1 = ri1[0];
    const float gm2 = rm2[0]; const int gi2 = ri2[0];
    __syncthreads();

    // --- rare-path double-precision refinement of argmin ---
    __shared__ int    s_code;
    __shared__ double sd[256];
    if (gm2 - gm1 < 1e-3f) {
        const float* x  = slot + (size_t)row * DIM;
        const float* c1 = cb + (size_t)gi1 * DIM;
        const float* c2 = cb + (size_t)gi2 * DIM;
        double d1 = 0.0, d2 = 0.0;
        for (int k = tid; k < DIM; k += 256) {
            double xv = (double)x[k];
            double a  = (double)c1[k];
            double b  = (double)c2[k];
            d1 += a * (a - 2.0 * xv);
            d2 += b * (b - 2.0 * xv);
        }
        sd[tid] = d1; __syncthreads();
        for (int s = 128; s > 0; s >>= 1) { if (tid < s) sd[tid] += sd[tid + s]; __syncthreads(); }
        double D1 = sd[0]; __syncthreads();
        sd[tid] = d2; __syncthreads();
        for (int s = 128; s > 0; s >>= 1) { if (tid < s) sd[tid] += sd[tid + s]; __syncthreads(); }
        double D2 = sd[0];
        if (tid == 0)
            s_code = (D2 < D1 || (D2 == D1 && gi2 < gi1)) ? gi2 : gi1;
    } else if (tid == 0) {
        s_code = gi1;
    }
    __syncthreads();
    const int code = s_code;

    // --- softmax over -s (row constant ||x||^2 cancels) ---
    float lsum = 0.f;
    #pragma unroll
    for (int i = 0; i < 16; i++) {
        float e = __expf(gm1 - v[i]);   // arg <= 0
        v[i] = e;
        lsum += e;
    }
    rm1[tid] = lsum; __syncthreads();
    for (int s = 128; s > 0; s >>= 1) { if (tid < s) rm1[tid] += rm1[tid + s]; __syncthreads(); }
    const float inv = 1.0f / rm1[0];
    float* probs = out + PROBS_OFF + (size_t)row * CB;
    #pragma unroll
    for (int i = 0; i < 16; i++)
        probs[tid + i * 256] = v[i] * inv;

    // --- quantized gather + loss contribution ---
    const float4* c4 = (const float4*)(cb + (size_t)code * DIM);
    const float4* x4 = (const float4*)(slot + (size_t)row * DIM);
    float4 q = c4[tid];
    float4 x = x4[tid];
    ((float4*)(out + QUANT_OFF + (size_t)row * DIM))[tid] = q;
    float dx = x.x - q.x, dy = x.y - q.y, dz = x.z - q.z, dw = x.w - q.w;
    float ls = dx * dx + dy * dy + dz * dz + dw * dw;

    __syncthreads();
    rm1[tid] = ls; __syncthreads();
    for (int s = 128; s > 0; s >>= 1) { if (tid < s) rm1[tid] += rm1[tid + s]; __syncthreads(); }
    if (tid == 0) {
        atomicAdd(&g_loss, (double)rm1[0]);
        out[CODES_OFF + row] = (float)code;
    }
}

// ---------------------------------------------------------------------------
// Kernel 3: finalize vq_loss = 1.25 * mean((x - q)^2)
// ---------------------------------------------------------------------------
__global__ void finish_kernel(float* __restrict__ out) {
    out[LOSS_OFF] = (float)(1.25 * g_loss / (double)((size_t)NROWS * DIM));
}

// ---------------------------------------------------------------------------
extern "C" void kernel_launch(void* const* d_in, const int* in_sizes, int n_in,
                              void* d_out, int out_size) {
    const float* slot = (const float*)d_in[0];   // [64,256,1024] f32
    const float* cb   = (const float*)d_in[1];   // [4096,1024]  f32
    float* out = (float*)d_out;

    // Dynamic smem opt-in (host-side attribute; idempotent; capture-safe)
    cudaFuncSetAttribute(gemm_kernel, cudaFuncAttributeMaxDynamicSharedMemorySize,
                         GEMM_SMEM_TOTAL);

    cnorm_kernel<<<CB, 256>>>(cb);
    split_kernel<<<(unsigned)((A_F4 + B_F4) / 256), 256>>>(slot, cb);
    dim3 grid(CB / GBN, NROWS / GBM);            // 32 x 128
    gemm_kernel<<<grid, 256, GEMM_SMEM_TOTAL>>>();
    row_kernel<<<NROWS, 256>>>(slot, cb, out);
    finish_kernel<<<1, 1>>>(out);
}